// round 11
// baseline (speedup 1.0000x reference)
#include <cuda_runtime.h>
#include <stdint.h>

// Problem shape is fixed: 32 images, 512x512, 1 channel, float32.
#define NIMG 32
#define H    512
#define WPX  512
#define WPR  16                       // 32-bit words per row (512/32)
#define NSEG 8                        // row-segments per image
#define SEGROWS 64                    // output rows per CTA
#define GHOST 16                      // ghost rows each side (= substep count)
#define EROWS 96                      // extended rows held in smem
#define TPB 192                       // 96 rows x 2 half-row strips
#define NWARPS (TPB / 32)             // 6 warps; warp w owns rows 16w..16w+15

__device__ __forceinline__ uint32_t maj3(uint32_t a, uint32_t b, uint32_t c) {
    return (a & b) | (c & (a | b));    // 1 LOP3
}

// Pairwise sync with vertically adjacent warps only (named barriers, 64 thr).
// A 2-warp barrier cannot skew more than one substep (32 arrivals < 64).
__device__ __forceinline__ void pairsync(int warp) {
    if (warp > 0)
        asm volatile("bar.sync %0, %1;" :: "r"(warp), "r"(64) : "memory");
    if (warp < NWARPS - 1)
        asm volatile("bar.sync %0, %1;" :: "r"(warp + 1), "r"(64) : "memory");
}

// Zhang-Suen delete mask for one 32-pixel word, given the 8 neighbor masks.
// acnt==1 computed as acnt<=1 (valid since 2<=bcnt<=6 implies acnt>=1).
template<bool FIRST>
__device__ __forceinline__ uint32_t word_update(
    uint32_t mi, uint32_t P2, uint32_t P3, uint32_t P4, uint32_t P5,
    uint32_t P6, uint32_t P7, uint32_t P8, uint32_t P9)
{
    // ---- bcnt via CSA: need 2 <= bcnt <= 6 ----
    uint32_t sa = P2 ^ P3 ^ P4, ca = maj3(P2, P3, P4);
    uint32_t sb = P5 ^ P6 ^ P7, cb = maj3(P5, P6, P7);
    uint32_t sc = P8 ^ P9,      cc = P8 & P9;
    uint32_t S0s = sa ^ sb ^ sc, C1 = maj3(sa, sb, sc);
    uint32_t S1s = ca ^ cb ^ cc, C2 = maj3(ca, cb, cc);
    uint32_t ge2 = C1 | S1s | C2;
    uint32_t ge7 = C2 & ((C1 & S1s) | ((C1 ^ S1s) & S0s));

    // ---- acnt <= 1: all carries of the transition CSA are zero ----
    uint32_t t0 = ~P2 & P3, t1 = ~P3 & P4, t2 = ~P4 & P5, t3 = ~P5 & P6;
    uint32_t t4 = ~P6 & P7, t5 = ~P7 & P8, t6 = ~P8 & P9, t7 = ~P9 & P2;
    uint32_t aca = maj3(t0, t1, t2);
    uint32_t acb = maj3(t3, t4, t5);
    uint32_t acc = t6 & t7;
    uint32_t asa = t0 ^ t1 ^ t2;
    uint32_t asb = t3 ^ t4 ^ t5;
    uint32_t asc = t6 ^ t7;
    uint32_t A1  = maj3(asa, asb, asc);
    uint32_t ex1 = ~(A1 | aca | acb) & ~acc;

    // ---- c1 & c2 ----
    uint32_t inner;
    if (FIRST) inner = (P4 & P6) & (P2 | P8);
    else       inner = (P2 & P8) & (P4 | P6);

    uint32_t del = ge2 & ~ge7 & ex1 & ~inner;
    return mi & ~del;
}

// Compute 8 output words (half h of smem row r): S -> D.
// Caller guarantees 1 <= r <= EROWS-2.
template<bool FIRST>
__device__ __forceinline__ void strip8(
    const uint32_t* __restrict__ S, uint32_t* __restrict__ D, int r, int h)
{
    int base = r * WPR + h * 8;

    uint32_t u[8], m[8], d[8], o[8];
    *(uint4*)&m[0] = *(const uint4*)&S[base];
    *(uint4*)&m[4] = *(const uint4*)&S[base + 4];
    *(uint4*)&u[0] = *(const uint4*)&S[base - WPR];
    *(uint4*)&u[4] = *(const uint4*)&S[base - WPR + 4];
    *(uint4*)&d[0] = *(const uint4*)&S[base + WPR];
    *(uint4*)&d[4] = *(const uint4*)&S[base + WPR + 4];
    uint32_t ml = h ? S[base - 1]       : 0u, mr = h ? 0u : S[base + 8];
    uint32_t ul = h ? S[base - WPR - 1] : 0u, ur = h ? 0u : S[base - WPR + 8];
    uint32_t dl = h ? S[base + WPR - 1] : 0u, dr = h ? 0u : S[base + WPR + 8];

    #pragma unroll
    for (int j = 0; j < 8; ++j) {
        uint32_t up = u[j], mi = m[j], dn = d[j];
        uint32_t upl = j ? u[j - 1] : ul, upr = (j < 7) ? u[j + 1] : ur;
        uint32_t mil = j ? m[j - 1] : ml, mir = (j < 7) ? m[j + 1] : mr;
        uint32_t dnl = j ? d[j - 1] : dl, dnr = (j < 7) ? d[j + 1] : dr;

        uint32_t P2 = up;
        uint32_t P3 = __funnelshift_r(up, upr, 1);
        uint32_t P4 = __funnelshift_r(mi, mir, 1);
        uint32_t P5 = __funnelshift_r(dn, dnr, 1);
        uint32_t P6 = dn;
        uint32_t P7 = __funnelshift_l(dnl, dn, 1);
        uint32_t P8 = __funnelshift_l(mil, mi, 1);
        uint32_t P9 = __funnelshift_l(upl, up, 1);

        o[j] = word_update<FIRST>(mi, P2, P3, P4, P5, P6, P7, P8, P9);
    }

    *(uint4*)&D[base]     = make_uint4(o[0], o[1], o[2], o[3]);
    *(uint4*)&D[base + 4] = make_uint4(o[4], o[5], o[6], o[7]);
}

// ---------------------------------------------------------------------------
// Fully fused kernel, pairwise warp sync only, 8 words per thread.
// 256 independent CTAs (32 images x 8 segments of 64 rows + 16 ghosts/side).
// Warp w owns extended rows 16w..16w+15 through all phases:
//   pack own rows -> pairsync -> 15 x (substep, pairsync) -> substep 16
//   -> __syncwarp -> unpack own rows (warps 1..4 = rows 16..79 exactly).
// ---------------------------------------------------------------------------
__global__ void __launch_bounds__(TPB, 3)
fused_skeleton_kernel(const float* __restrict__ in, float* __restrict__ out) {
    __shared__ uint32_t S0[EROWS * WPR];
    __shared__ uint32_t S1[EROWS * WPR];

    int tid  = threadIdx.x;
    int warp = tid >> 5;
    int lane = tid & 31;
    int img  = blockIdx.x >> 3;
    int seg  = blockIdx.x & 7;
    int segrow0 = seg * SEGROWS - GHOST;            // global row of ext row 0

    // ---- Pack phase: warp w ballots its extended rows 16w..16w+15 ----
    {
        #pragma unroll 1
        for (int rr = 0; rr < 16; ++rr) {
            int r    = warp * 16 + rr;              // extended row 0..95
            int grow = segrow0 + r;
            bool valid = (grow >= 0) && (grow < H);
            const float* p = in + ((size_t)img * H + (valid ? grow : 0)) * WPX + lane;
            float v[16];
            #pragma unroll
            for (int i = 0; i < 16; ++i)            // MLP = 16
                v[i] = valid ? p[i * 32] : 0.0f;
            #pragma unroll
            for (int i = 0; i < 16; ++i) {
                uint32_t b = __ballot_sync(0xffffffffu, v[i] >= 0.5f);
                if (lane == 0) S0[r * WPR + i] = b;
            }
        }
    }
    pairsync(warp);

    // ---- 16 substeps, shrinking window, pairwise sync only ----
    int r = tid >> 1;                 // extended row 0..95 (warp w: 16w..16w+15)
    int h = tid & 1;                  // half-row
    #pragma unroll 1
    for (int k = 1; k <= 15; ++k) {
        bool active = (r >= k) && (r <= EROWS - 1 - k);
        if (k & 1) { if (active) strip8<true >(S0, S1, r, h); }
        else       { if (active) strip8<false>(S1, S0, r, h); }
        pairsync(warp);
    }
    {   // k = 16 (even: S1 -> S0). After this, each warp only reads rows it
        // computed itself, so intra-warp sync suffices.
        bool active = (r >= 16) && (r <= EROWS - 1 - 16);
        if (active) strip8<false>(S1, S0, r, h);
        __syncwarp();
    }

    // ---- Unpack phase: warps 1..4 write their own rows (ext 16..79) ----
    if (warp >= 1 && warp <= 4) {
        float* obase = out + ((size_t)img * H + seg * SEGROWS) * WPX;
        #pragma unroll 1
        for (int rr = 0; rr < 16; ++rr) {
            int row = warp * 16 + rr;               // extended row 16..79
            float4* o4 = (float4*)(obase + (size_t)(row - GHOST) * WPX);
            #pragma unroll
            for (int j = 0; j < 4; ++j) {           // 512B contiguous per STG
                uint32_t w = S0[row * WPR + j * 4 + (lane >> 3)];
                int sh = (lane & 7) * 4;
                float4 f;
                f.x = __uint_as_float(((w >> (sh + 0)) & 1u) * 0x3F800000u);
                f.y = __uint_as_float(((w >> (sh + 1)) & 1u) * 0x3F800000u);
                f.z = __uint_as_float(((w >> (sh + 2)) & 1u) * 0x3F800000u);
                f.w = __uint_as_float(((w >> (sh + 3)) & 1u) * 0x3F800000u);
                o4[j * 32 + lane] = f;
            }
        }
    }
}

extern "C" void kernel_launch(void* const* d_in, const int* in_sizes, int n_in,
                              void* d_out, int out_size) {
    (void)in_sizes; (void)n_in; (void)out_size;
    const float* in = (const float*)d_in[0];
    float* out = (float*)d_out;

    fused_skeleton_kernel<<<NIMG * NSEG, TPB>>>(in, out);
}

// round 12
// speedup vs baseline: 1.2267x; 1.2267x over previous
#include <cuda_runtime.h>
#include <stdint.h>

// Problem shape is fixed: 32 images, 512x512, 1 channel, float32.
#define NIMG 32
#define H    512
#define WPX  512
#define WPR  16                       // 32-bit words per row (512/32)
#define NSEG 8                        // row-segments per image
#define SEGROWS 64                    // output rows per CTA
#define GHOST 16                      // ghost rows each side (= substep count)
#define EROWS 96                      // extended rows held in smem
#define TPB 384                       // 12 warps x 8 rows, 4 quarter-strips/row
#define NWARPS (TPB / 32)

__device__ __forceinline__ uint32_t maj3(uint32_t a, uint32_t b, uint32_t c) {
    return (a & b) | (c & (a | b));    // 1 LOP3
}

// Pairwise sync with vertically adjacent warps only (named barriers, 64 thr).
// A 2-warp barrier cannot skew more than one substep (32 arrivals < 64).
__device__ __forceinline__ void pairsync(int warp) {
    if (warp > 0)
        asm volatile("bar.sync %0, %1;" :: "r"(warp), "r"(64) : "memory");
    if (warp < NWARPS - 1)
        asm volatile("bar.sync %0, %1;" :: "r"(warp + 1), "r"(64) : "memory");
}

// Zhang-Suen DELETE mask for one 32-pixel word, given the 8 neighbor masks.
// acnt==1 computed as acnt<=1 (valid since 2<=bcnt<=6 implies acnt>=1).
template<bool FIRST>
__device__ __forceinline__ uint32_t word_delete(
    uint32_t mi, uint32_t P2, uint32_t P3, uint32_t P4, uint32_t P5,
    uint32_t P6, uint32_t P7, uint32_t P8, uint32_t P9)
{
    // ---- bcnt via CSA: need 2 <= bcnt <= 6 ----
    uint32_t sa = P2 ^ P3 ^ P4, ca = maj3(P2, P3, P4);
    uint32_t sb = P5 ^ P6 ^ P7, cb = maj3(P5, P6, P7);
    uint32_t sc = P8 ^ P9,      cc = P8 & P9;
    uint32_t S0s = sa ^ sb ^ sc, C1 = maj3(sa, sb, sc);
    uint32_t S1s = ca ^ cb ^ cc, C2 = maj3(ca, cb, cc);
    uint32_t ge2 = C1 | S1s | C2;
    uint32_t ge7 = C2 & ((C1 & S1s) | ((C1 ^ S1s) & S0s));

    // ---- acnt <= 1: all carries of the transition CSA are zero ----
    uint32_t t0 = ~P2 & P3, t1 = ~P3 & P4, t2 = ~P4 & P5, t3 = ~P5 & P6;
    uint32_t t4 = ~P6 & P7, t5 = ~P7 & P8, t6 = ~P8 & P9, t7 = ~P9 & P2;
    uint32_t aca = maj3(t0, t1, t2);
    uint32_t acb = maj3(t3, t4, t5);
    uint32_t acc = t6 & t7;
    uint32_t asa = t0 ^ t1 ^ t2;
    uint32_t asb = t3 ^ t4 ^ t5;
    uint32_t asc = t6 ^ t7;
    uint32_t A1  = maj3(asa, asb, asc);
    uint32_t ex1 = ~(A1 | aca | acb) & ~acc;

    // ---- c1 & c2 ----
    uint32_t inner;
    if (FIRST) inner = (P4 & P6) & (P2 | P8);
    else       inner = (P2 & P8) & (P4 | P6);

    return mi & ge2 & ~ge7 & ex1 & ~inner;
}

// Compute 4 output words (quarter q of smem row r): S -> D.
// Returns OR of all delete bits produced (for convergence detection).
// Caller guarantees 1 <= r <= EROWS-2.
template<bool FIRST>
__device__ __forceinline__ uint32_t strip4(
    const uint32_t* __restrict__ S, uint32_t* __restrict__ D, int r, int q)
{
    int base = r * WPR + q * 4;

    uint4 m4 = *(const uint4*)&S[base];
    uint4 u4 = *(const uint4*)&S[base - WPR];
    uint4 d4 = *(const uint4*)&S[base + WPR];
    uint32_t ml = q ? S[base - 1]       : 0u, mr = (q < 3) ? S[base + 4]       : 0u;
    uint32_t ul = q ? S[base - WPR - 1] : 0u, ur = (q < 3) ? S[base - WPR + 4] : 0u;
    uint32_t dl = q ? S[base + WPR - 1] : 0u, dr = (q < 3) ? S[base + WPR + 4] : 0u;

    uint32_t u[4] = {u4.x, u4.y, u4.z, u4.w};
    uint32_t m[4] = {m4.x, m4.y, m4.z, m4.w};
    uint32_t d[4] = {d4.x, d4.y, d4.z, d4.w};
    uint32_t o[4];
    uint32_t dacc = 0;

    #pragma unroll
    for (int j = 0; j < 4; ++j) {
        uint32_t up = u[j], mi = m[j], dn = d[j];
        uint32_t upl = j ? u[j - 1] : ul, upr = (j < 3) ? u[j + 1] : ur;
        uint32_t mil = j ? m[j - 1] : ml, mir = (j < 3) ? m[j + 1] : mr;
        uint32_t dnl = j ? d[j - 1] : dl, dnr = (j < 3) ? d[j + 1] : dr;

        uint32_t P2 = up;
        uint32_t P3 = __funnelshift_r(up, upr, 1);
        uint32_t P4 = __funnelshift_r(mi, mir, 1);
        uint32_t P5 = __funnelshift_r(dn, dnr, 1);
        uint32_t P6 = dn;
        uint32_t P7 = __funnelshift_l(dnl, dn, 1);
        uint32_t P8 = __funnelshift_l(mil, mi, 1);
        uint32_t P9 = __funnelshift_l(upl, up, 1);

        uint32_t del = word_delete<FIRST>(mi, P2, P3, P4, P5, P6, P7, P8, P9);
        dacc |= del;
        o[j] = mi & ~del;
    }

    *(uint4*)&D[base] = make_uint4(o[0], o[1], o[2], o[3]);
    return dacc;
}

// ---------------------------------------------------------------------------
// Fully fused kernel: pairwise warp sync on odd substeps, CTA sync on even
// substeps (doubling as the convergence-check point).
// 256 independent CTAs (32 images x 8 segments of 64 rows + 16 ghosts/side).
// Shrinking window [k, 95-k] contains exactly the rows that are exact at
// substep k, so the delete-flag only sees real deletions. If substeps k-1
// and k both deleted nothing, the state is a fixed point of both rules and
// all remaining substeps are identities -> break (even k only: result in S0).
// ---------------------------------------------------------------------------
__global__ void __launch_bounds__(TPB, 2)
fused_skeleton_kernel(const float* __restrict__ in, float* __restrict__ out) {
    __shared__ uint32_t S0[EROWS * WPR];
    __shared__ uint32_t S1[EROWS * WPR];
    __shared__ int sflags[17];

    int tid  = threadIdx.x;
    int warp = tid >> 5;
    int lane = tid & 31;
    int img  = blockIdx.x >> 3;
    int seg  = blockIdx.x & 7;
    int segrow0 = seg * SEGROWS - GHOST;            // global row of ext row 0

    if (tid < 17) sflags[tid] = 0;

    // ---- Pack phase: warp w ballots its extended rows 8w..8w+7 ----
    {
        #pragma unroll 1
        for (int rr = 0; rr < 8; ++rr) {
            int r    = warp * 8 + rr;               // extended row 0..95
            int grow = segrow0 + r;
            bool valid = (grow >= 0) && (grow < H);
            const float* p = in + ((size_t)img * H + (valid ? grow : 0)) * WPX + lane;
            float v[16];
            #pragma unroll
            for (int i = 0; i < 16; ++i)            // MLP = 16
                v[i] = valid ? p[i * 32] : 0.0f;
            #pragma unroll
            for (int i = 0; i < 16; ++i) {
                uint32_t b = __ballot_sync(0xffffffffu, v[i] >= 0.5f);
                if (lane == 0) S0[r * WPR + i] = b;
            }
        }
    }
    __syncthreads();    // orders pack stores + flag init CTA-wide

    // ---- up to 16 substeps, shrinking window, early convergence exit ----
    int r = tid >> 2;                 // extended row 0..95 (warp w: 8w..8w+7)
    int q = tid & 3;                  // quarter-row
    #pragma unroll 1
    for (int k = 1; k <= 16; ++k) {
        bool active = (r >= k) && (r <= EROWS - 1 - k);
        uint32_t dOR = 0;
        if (k & 1) { if (active) dOR = strip4<true >(S0, S1, r, q); }
        else       { if (active) dOR = strip4<false>(S1, S0, r, q); }

        unsigned anym = __ballot_sync(0xffffffffu, dOR != 0u);
        if (anym && lane == 0) sflags[k] = 1;       // benign same-value race

        if (k & 1) {
            pairsync(warp);
        } else {
            __syncthreads();                        // flags + data visible
            if (sflags[k - 1] == 0 && sflags[k] == 0) break;   // fixed point
        }
    }
    // Loop exits only at even k: final state in S0; exact rows are 16..79.

    // ---- Unpack phase: warps 2..9 write their own rows (ext 16..79) ----
    if (warp >= 2 && warp <= 9) {
        float* obase = out + ((size_t)img * H + seg * SEGROWS) * WPX;
        #pragma unroll
        for (int rr = 0; rr < 8; ++rr) {
            int row  = warp * 8 + rr;               // extended row 16..79
            float4* o4 = (float4*)(obase + (size_t)(row - GHOST) * WPX);
            #pragma unroll
            for (int j = 0; j < 4; ++j) {           // 512B contiguous per STG
                uint32_t w = S0[row * WPR + j * 4 + (lane >> 3)];
                int sh = (lane & 7) * 4;
                float4 f;
                f.x = __uint_as_float(((w >> (sh + 0)) & 1u) * 0x3F800000u);
                f.y = __uint_as_float(((w >> (sh + 1)) & 1u) * 0x3F800000u);
                f.z = __uint_as_float(((w >> (sh + 2)) & 1u) * 0x3F800000u);
                f.w = __uint_as_float(((w >> (sh + 3)) & 1u) * 0x3F800000u);
                o4[j * 32 + lane] = f;
            }
        }
    }
}

extern "C" void kernel_launch(void* const* d_in, const int* in_sizes, int n_in,
                              void* d_out, int out_size) {
    (void)in_sizes; (void)n_in; (void)out_size;
    const float* in = (const float*)d_in[0];
    float* out = (float*)d_out;

    fused_skeleton_kernel<<<NIMG * NSEG, TPB>>>(in, out);
}